// round 13
// baseline (speedup 1.0000x reference)
#include <cuda_runtime.h>
#include <cuda_fp16.h>

// Fixed problem shape: N=50000, E=1600000, D=U=128.
#define MAX_N 50048
#define MAX_E 1600000
#define D_DIM 128

#define SCAN_BLK   256
#define SCAN_ITEMS 16
#define SCAN_TILE  (SCAN_BLK * SCAN_ITEMS)   // 4096
#define MAX_SCAN_BLKS 16

// Packed fp32x2 FMA (Blackwell): one issue slot, two IEEE fp32 FMAs.
#define FMA_F32X2(d, a, b, c) \
    asm("fma.rn.f32x2 %0, %1, %2, %3;" : "=l"(d) : "l"(a), "l"(b), "l"(c))
#define PACK_F32X2(d, lo, hi) \
    asm("mov.b64 %0, {%1, %2};" : "=l"(d) : "f"(lo), "f"(hi))
#define UNPACK_F32X2(lo, hi, s) \
    asm("mov.b64 {%0, %1}, %2;" : "=f"(lo), "=f"(hi) : "l"(s))

// Scratch (__device__ globals; no allocations allowed).
__device__ int    g_counts[MAX_N];
__device__ int    g_offsets[MAX_N + 1];
__device__ int    g_cursor[MAX_N];
__device__ int    g_blocksum[MAX_SCAN_BLKS];   // inclusive per-block sums
__device__ int    g_flags[MAX_SCAN_BLKS];      // lookback ready flags
__device__ int2   g_edges[MAX_E];              // (dst, weight bits), CSR by src
__device__ __half g_featH[(size_t)MAX_N * D_DIM];

// ---------------------------------------------------------------------------
// fp32 -> fp16 feature table (2 float4 per thread), fused with zeroing.
__global__ void prep_kernel(const float* __restrict__ feat, int total4, int N) {
    int i = (blockIdx.x * blockDim.x + threadIdx.x) * 2;
#pragma unroll
    for (int u = 0; u < 2; u++) {
        int idx = i + u;
        if (idx < total4) {
            float4 v = ((const float4*)feat)[idx];
            __half2 h0 = __floats2half2_rn(v.x, v.y);
            __half2 h1 = __floats2half2_rn(v.z, v.w);
            uint2 uu;
            *reinterpret_cast<__half2*>(&uu.x) = h0;
            *reinterpret_cast<__half2*>(&uu.y) = h1;
            ((uint2*)g_featH)[idx] = uu;
        }
    }
    int t = blockIdx.x * blockDim.x + threadIdx.x;
    if (t < N) g_counts[t] = 0;
    if (t < MAX_SCAN_BLKS) { g_flags[t] = 0; g_blocksum[t] = 0; }
}

// histogram of edge_src, 8 edges/thread for atomic ILP
__global__ void hist_kernel(const int* __restrict__ src, int E) {
    int i = (blockIdx.x * blockDim.x + threadIdx.x) * 8;
    if (i + 8 <= E) {
        int4 s0 = *(const int4*)(src + i);
        int4 s1 = *(const int4*)(src + i + 4);
        atomicAdd(&g_counts[s0.x], 1);
        atomicAdd(&g_counts[s0.y], 1);
        atomicAdd(&g_counts[s0.z], 1);
        atomicAdd(&g_counts[s0.w], 1);
        atomicAdd(&g_counts[s1.x], 1);
        atomicAdd(&g_counts[s1.y], 1);
        atomicAdd(&g_counts[s1.z], 1);
        atomicAdd(&g_counts[s1.w], 1);
    } else {
        for (int j = i; j < E; j++) atomicAdd(&g_counts[src[j]], 1);
    }
}

// ---- single-pass exclusive scan (decoupled lookback; nblk=13 <= #SMs) ----
__global__ void scan_kernel(int N, int nblk) {
    __shared__ int swarp[SCAN_BLK / 32];
    __shared__ int s_prev;
    const int tid = threadIdx.x, lane = tid & 31, wid = tid >> 5;
    const int b = blockIdx.x;
    int start = b * SCAN_TILE + tid * SCAN_ITEMS;

    int vals[SCAN_ITEMS];
    int local = 0;
    if (start + SCAN_ITEMS <= N) {
#pragma unroll
        for (int v = 0; v < SCAN_ITEMS / 4; v++) {
            int4 c = *(const int4*)(g_counts + start + v * 4);
            vals[v * 4 + 0] = c.x; vals[v * 4 + 1] = c.y;
            vals[v * 4 + 2] = c.z; vals[v * 4 + 3] = c.w;
            local += c.x + c.y + c.z + c.w;
        }
    } else {
#pragma unroll
        for (int i = 0; i < SCAN_ITEMS; i++) {
            int idx = start + i;
            vals[i] = (idx < N) ? g_counts[idx] : 0;
            local += vals[i];
        }
    }
    int x = local;
#pragma unroll
    for (int off = 1; off < 32; off <<= 1) {
        int y = __shfl_up_sync(0xffffffffu, x, off);
        if (lane >= off) x += y;
    }
    if (lane == 31) swarp[wid] = x;
    __syncthreads();
    if (wid == 0 && lane < SCAN_BLK / 32) {
        int v = swarp[lane];
        int xv = v;
#pragma unroll
        for (int off = 1; off < SCAN_BLK / 32; off <<= 1) {
            int y = __shfl_up_sync(0xffu, xv, off);
            if (lane >= off) xv += y;
        }
        swarp[lane] = xv - v;   // exclusive warp prefix
    }
    __syncthreads();
    int within = swarp[wid] + (x - local);       // exclusive prefix within block
    int blktot = 0;
    if (tid == SCAN_BLK - 1) blktot = within + local;

    if (tid == SCAN_BLK - 1) {
        int prev = 0;
        if (b > 0) {
            while (atomicAdd(&g_flags[b - 1], 0) == 0) { }
            prev = g_blocksum[b - 1];
        }
        g_blocksum[b] = prev + blktot;
        __threadfence();
        atomicExch(&g_flags[b], 1);
        s_prev = prev;
        if (b == nblk - 1) g_offsets[N] = prev + blktot;
    }
    __syncthreads();
    int pre = s_prev + within;
    if (start + SCAN_ITEMS <= N) {
#pragma unroll
        for (int i = 0; i < SCAN_ITEMS; i++) {
            g_offsets[start + i] = pre;
            g_cursor[start + i] = pre;
            pre += vals[i];
        }
    } else {
        for (int i = 0; i < SCAN_ITEMS; i++) {
            int idx = start + i;
            if (idx < N) { g_offsets[idx] = pre; g_cursor[idx] = pre; }
            pre += vals[i];
        }
    }
}

// scatter edges into CSR order, 8 edges/thread: 8 independent
// LDG -> ATOMG -> STG chains in flight per thread (latency-bound kernel).
__global__ void scatter_kernel(const int* __restrict__ src,
                               const int* __restrict__ dst,
                               const float* __restrict__ w, int E) {
    int i = (blockIdx.x * blockDim.x + threadIdx.x) * 8;
    if (i + 8 <= E) {
        int4   s0 = *(const int4*)(src + i);
        int4   s1 = *(const int4*)(src + i + 4);
        int4   d0 = *(const int4*)(dst + i);
        int4   d1 = *(const int4*)(dst + i + 4);
        float4 w0 = *(const float4*)(w + i);
        float4 w1 = *(const float4*)(w + i + 4);
        int p0 = atomicAdd(&g_cursor[s0.x], 1);
        int p1 = atomicAdd(&g_cursor[s0.y], 1);
        int p2 = atomicAdd(&g_cursor[s0.z], 1);
        int p3 = atomicAdd(&g_cursor[s0.w], 1);
        int p4 = atomicAdd(&g_cursor[s1.x], 1);
        int p5 = atomicAdd(&g_cursor[s1.y], 1);
        int p6 = atomicAdd(&g_cursor[s1.z], 1);
        int p7 = atomicAdd(&g_cursor[s1.w], 1);
        g_edges[p0] = make_int2(d0.x, __float_as_int(w0.x));
        g_edges[p1] = make_int2(d0.y, __float_as_int(w0.y));
        g_edges[p2] = make_int2(d0.z, __float_as_int(w0.z));
        g_edges[p3] = make_int2(d0.w, __float_as_int(w0.w));
        g_edges[p4] = make_int2(d1.x, __float_as_int(w1.x));
        g_edges[p5] = make_int2(d1.y, __float_as_int(w1.y));
        g_edges[p6] = make_int2(d1.z, __float_as_int(w1.z));
        g_edges[p7] = make_int2(d1.w, __float_as_int(w1.w));
    } else {
        for (int j = i; j < E; j++) {
            int p = atomicAdd(&g_cursor[src[j]], 1);
            g_edges[p] = make_int2(dst[j], __float_as_int(w[j]));
        }
    }
}

// ---------------------------------------------------------------------------
// Fused aggregate (fp16 gather, depth-2 pipelined) + GEMM (FFMA2) + bias + relu.
// 512 threads (16 warps) share ONE smem W tile -> 32 warps/SM at 2 blocks/SM.
// (regfile-capped: 1024 thr/SM x 64 regs = full 64K regfile)
#define ROWS_PER_WARP 4
#define FWARPS 16
#define FTHREADS (FWARPS * 32)          // 512
#define FTILE (FWARPS * ROWS_PER_WARP)  // 64 nodes per block-tile

__global__ __launch_bounds__(FTHREADS, 2)
void fused_agg_gemm_kernel(const float* __restrict__ W,
                           const float* __restrict__ b,
                           float* __restrict__ out, int N) {
    extern __shared__ float sh[];
    float* Ws   = sh;                            // [128][128]
    float* bs   = Ws + D_DIM * D_DIM;            // [128]
    float* aggs = bs + D_DIM;                    // [16][4][128]

    const int tid = threadIdx.x;
    const float4* Wv = (const float4*)W;
    float4* Wsv = (float4*)Ws;
#pragma unroll
    for (int i = 0; i < 8; i++) Wsv[tid + i * FTHREADS] = Wv[tid + i * FTHREADS];
    if (tid < D_DIM) bs[tid] = b[tid];
    __syncthreads();

    const int warp = tid >> 5, lane = tid & 31;
    float* myagg = aggs + warp * ROWS_PER_WARP * D_DIM;
    const uint2* fH = (const uint2*)g_featH;

    const int tiles = (N + FTILE - 1) / FTILE;
    for (int t = blockIdx.x; t < tiles; t += gridDim.x) {
        const int base = t * FTILE + warp * ROWS_PER_WARP;

        // ---- gather phase: weighted mean per node row, depth-2 pipeline ----
#pragma unroll
        for (int r = 0; r < ROWS_PER_WARP; r++) {
            int node = base + r;
            unsigned long long sAB = 0ull, sCD = 0ull;   // packed (x,y),(z,w)
            float den = 0.f;
            if (node < N) {
                const int beg = g_offsets[node], end = g_offsets[node + 1];
                const int nch = (end - beg + 3) >> 2;    // masked 4-edge chunks
                if (nch > 0) {
#define LDE(a0, a1, a2, a3, jj) do {                                          \
    a0 = ((jj) + 0 < end) ? g_edges[(jj) + 0] : make_int2(0, 0);              \
    a1 = ((jj) + 1 < end) ? g_edges[(jj) + 1] : make_int2(0, 0);              \
    a2 = ((jj) + 2 < end) ? g_edges[(jj) + 2] : make_int2(0, 0);              \
    a3 = ((jj) + 3 < end) ? g_edges[(jj) + 3] : make_int2(0, 0);              \
} while (0)
#define LDH(x0, x1, x2, x3, a0, a1, a2, a3) do {                              \
    x0 = fH[(size_t)(a0).x * 32 + lane];                                      \
    x1 = fH[(size_t)(a1).x * 32 + lane];                                      \
    x2 = fH[(size_t)(a2).x * 32 + lane];                                      \
    x3 = fH[(size_t)(a3).x * 32 + lane];                                      \
} while (0)
#define EDGE_ACC(hh, wsc) do {                                                \
    float2 p_ = __half22float2(*reinterpret_cast<__half2*>(&(hh).x));         \
    float2 q_ = __half22float2(*reinterpret_cast<__half2*>(&(hh).y));         \
    unsigned long long pp_, qq_, ww_;                                         \
    PACK_F32X2(pp_, p_.x, p_.y);                                              \
    PACK_F32X2(qq_, q_.x, q_.y);                                              \
    PACK_F32X2(ww_, (wsc), (wsc));                                            \
    FMA_F32X2(sAB, ww_, pp_, sAB);                                            \
    FMA_F32X2(sCD, ww_, qq_, sCD);                                            \
} while (0)
#define ACC4() do {                                                           \
    float w0_ = __int_as_float(e0.y), w1_ = __int_as_float(e1.y);             \
    float w2_ = __int_as_float(e2.y), w3_ = __int_as_float(e3.y);             \
    EDGE_ACC(h0, w0_); EDGE_ACC(h1, w1_);                                     \
    EDGE_ACC(h2, w2_); EDGE_ACC(h3, w3_);                                     \
    den += (w0_ + w1_) + (w2_ + w3_);                                         \
} while (0)
                    int2 e0, e1, e2, e3;      // edges: chunk c (being accumulated)
                    int2 f0, f1, f2, f3;      // edges: chunk c+1 (features pending)
                    uint2 h0, h1, h2, h3;     // features: chunk c
                    int j = beg;
                    LDE(e0, e1, e2, e3, j);               // chunk 0 edges
                    LDH(h0, h1, h2, h3, e0, e1, e2, e3);  // chunk 0 features
                    j += 4;
                    if (nch > 1) LDE(f0, f1, f2, f3, j);  // chunk 1 edges
                    for (int c = 0; c + 2 < nch; c++) {
                        j += 4;
                        int2 g0, g1, g2, g3;
                        LDE(g0, g1, g2, g3, j);           // chunk c+2 edges
                        uint2 n0, n1, n2, n3;
                        LDH(n0, n1, n2, n3, f0, f1, f2, f3);  // chunk c+1 feats
                        ACC4();                            // accumulate chunk c
                        e0 = f0; e1 = f1; e2 = f2; e3 = f3;
                        f0 = g0; f1 = g1; f2 = g2; f3 = g3;
                        h0 = n0; h1 = n1; h2 = n2; h3 = n3;
                    }
                    if (nch > 1) {
                        uint2 n0, n1, n2, n3;
                        LDH(n0, n1, n2, n3, f0, f1, f2, f3);  // last chunk feats
                        ACC4();                                // chunk nch-2
                        e0 = f0; e1 = f1; e2 = f2; e3 = f3;
                        h0 = n0; h1 = n1; h2 = n2; h3 = n3;
                    }
                    ACC4();                                    // last chunk
#undef ACC4
#undef EDGE_ACC
#undef LDH
#undef LDE
                }
            }
            float ax, ay, az, aw;
            UNPACK_F32X2(ax, ay, sAB);
            UNPACK_F32X2(az, aw, sCD);
            float inv = 1.0f / fmaxf(den, 1e-12f);
            *(float4*)(myagg + r * D_DIM + lane * 4) =
                make_float4(ax * inv, ay * inv, az * inv, aw * inv);
        }
        __syncwarp();

        // ---- GEMM phase: packed FFMA2, 4 rows x 4 cols per thread ----
        unsigned long long accA[ROWS_PER_WARP], accB[ROWS_PER_WARP];
#pragma unroll
        for (int r = 0; r < ROWS_PER_WARP; r++) { accA[r] = 0ull; accB[r] = 0ull; }

#pragma unroll 8
        for (int k = 0; k < D_DIM; k += 4) {
            float4 a[ROWS_PER_WARP];
#pragma unroll
            for (int r = 0; r < ROWS_PER_WARP; r++)
                a[r] = *(float4*)(myagg + r * D_DIM + k);
#pragma unroll
            for (int kk = 0; kk < 4; kk++) {
                ulonglong2 wp = *(ulonglong2*)(Ws + (k + kk) * D_DIM + lane * 4);
#pragma unroll
                for (int r = 0; r < ROWS_PER_WARP; r++) {
                    float av = ((float*)&a[r])[kk];
                    unsigned long long avv;
                    PACK_F32X2(avv, av, av);
                    FMA_F32X2(accA[r], avv, wp.x, accA[r]);
                    FMA_F32X2(accB[r], avv, wp.y, accB[r]);
                }
            }
        }

        float4 bb = *(float4*)(bs + lane * 4);
#pragma unroll
        for (int r = 0; r < ROWS_PER_WARP; r++) {
            int row = base + r;
            if (row < N) {
                float ox, oy, oz, ow;
                UNPACK_F32X2(ox, oy, accA[r]);
                UNPACK_F32X2(oz, ow, accB[r]);
                float4 o;
                o.x = fmaxf(ox + bb.x, 0.f);
                o.y = fmaxf(oy + bb.y, 0.f);
                o.z = fmaxf(oz + bb.z, 0.f);
                o.w = fmaxf(ow + bb.w, 0.f);
                *(float4*)(out + (size_t)row * D_DIM + lane * 4) = o;
            }
        }
        __syncwarp();
    }
}

// ---------------------------------------------------------------------------
extern "C" void kernel_launch(void* const* d_in, const int* in_sizes, int n_in,
                              void* d_out, int out_size) {
    const float* feat = (const float*)d_in[0];   // [N,128]
    const int*   src  = (const int*)d_in[1];     // [E]
    const int*   dst  = (const int*)d_in[2];     // [E]
    const float* w    = (const float*)d_in[3];   // [E]
    const float* W    = (const float*)d_in[4];   // [128,128]
    const float* b    = (const float*)d_in[5];   // [128]
    float* out = (float*)d_out;

    const int N = in_sizes[0] / D_DIM;
    const int E = in_sizes[1];

    {
        int total4 = N * (D_DIM / 4);
        int nthread = (total4 + 1) / 2;
        prep_kernel<<<(nthread + 255) / 256, 256>>>(feat, total4, N);
    }
    hist_kernel<<<((E + 7) / 8 + 255) / 256, 256>>>(src, E);

    const int nblk = (N + SCAN_TILE - 1) / SCAN_TILE;   // 13 (<= #SMs: safe lookback)
    scan_kernel<<<nblk, SCAN_BLK>>>(N, nblk);

    scatter_kernel<<<((E + 7) / 8 + 255) / 256, 256>>>(src, dst, w, E);

    const int smem = (D_DIM * D_DIM + D_DIM +
                      FWARPS * ROWS_PER_WARP * D_DIM) * (int)sizeof(float);  // 98816 B
    cudaFuncSetAttribute(fused_agg_gemm_kernel,
                         cudaFuncAttributeMaxDynamicSharedMemorySize, smem);
    fused_agg_gemm_kernel<<<296, FTHREADS, smem>>>(W, b, out, N);
}

// round 15
// speedup vs baseline: 1.4288x; 1.4288x over previous
#include <cuda_runtime.h>
#include <cuda_fp16.h>

// Fixed problem shape: N=50000, E=1600000, D=U=128.
#define MAX_N 50048
#define MAX_E 1600000
#define D_DIM 128

#define SCAN_BLK   256
#define SCAN_ITEMS 16
#define SCAN_TILE  (SCAN_BLK * SCAN_ITEMS)   // 4096
#define MAX_SCAN_BLKS 16

// Packed fp32x2 FMA (Blackwell): one issue slot, two IEEE fp32 FMAs.
#define FMA_F32X2(d, a, b, c) \
    asm("fma.rn.f32x2 %0, %1, %2, %3;" : "=l"(d) : "l"(a), "l"(b), "l"(c))
#define PACK_F32X2(d, lo, hi) \
    asm("mov.b64 %0, {%1, %2};" : "=l"(d) : "f"(lo), "f"(hi))
#define UNPACK_F32X2(lo, hi, s) \
    asm("mov.b64 {%0, %1}, %2;" : "=f"(lo), "=f"(hi) : "l"(s))

// Scratch (__device__ globals; no allocations allowed).
__device__ int    g_counts[MAX_N];
__device__ int    g_offsets[MAX_N + 1];
__device__ int    g_cursor[MAX_N];
__device__ int    g_blocksum[MAX_SCAN_BLKS];   // inclusive per-block sums
__device__ int    g_flags[MAX_SCAN_BLKS];      // lookback ready flags
__device__ int2   g_edges[MAX_E];              // (dst, weight bits), CSR by src
__device__ __half g_featH[(size_t)MAX_N * D_DIM];

// ---------------------------------------------------------------------------
// fp32 -> fp16 feature table, fused with zeroing counts + scan flags.
__global__ void prep_kernel(const float* __restrict__ feat, int total4, int N) {
    int i = blockIdx.x * blockDim.x + threadIdx.x;
    if (i < total4) {
        float4 v = ((const float4*)feat)[i];
        __half2 h0 = __floats2half2_rn(v.x, v.y);
        __half2 h1 = __floats2half2_rn(v.z, v.w);
        uint2 u;
        *reinterpret_cast<__half2*>(&u.x) = h0;
        *reinterpret_cast<__half2*>(&u.y) = h1;
        ((uint2*)g_featH)[i] = u;
    }
    if (i < N) g_counts[i] = 0;
    if (i < MAX_SCAN_BLKS) { g_flags[i] = 0; g_blocksum[i] = 0; }
}

// histogram of edge_src, 4 edges/thread
__global__ void hist_kernel(const int* __restrict__ src, int E) {
    int i = (blockIdx.x * blockDim.x + threadIdx.x) * 4;
    if (i + 4 <= E) {
        int4 s = *(const int4*)(src + i);
        atomicAdd(&g_counts[s.x], 1);
        atomicAdd(&g_counts[s.y], 1);
        atomicAdd(&g_counts[s.z], 1);
        atomicAdd(&g_counts[s.w], 1);
    } else {
        for (int j = i; j < E; j++) atomicAdd(&g_counts[src[j]], 1);
    }
}

// ---- single-pass exclusive scan (decoupled lookback; nblk=13 <= #SMs) ----
__global__ void scan_kernel(int N, int nblk) {
    __shared__ int swarp[SCAN_BLK / 32];
    __shared__ int s_prev;
    const int tid = threadIdx.x, lane = tid & 31, wid = tid >> 5;
    const int b = blockIdx.x;
    int start = b * SCAN_TILE + tid * SCAN_ITEMS;

    int vals[SCAN_ITEMS];
    int local = 0;
    if (start + SCAN_ITEMS <= N) {
#pragma unroll
        for (int v = 0; v < SCAN_ITEMS / 4; v++) {
            int4 c = *(const int4*)(g_counts + start + v * 4);
            vals[v * 4 + 0] = c.x; vals[v * 4 + 1] = c.y;
            vals[v * 4 + 2] = c.z; vals[v * 4 + 3] = c.w;
            local += c.x + c.y + c.z + c.w;
        }
    } else {
#pragma unroll
        for (int i = 0; i < SCAN_ITEMS; i++) {
            int idx = start + i;
            vals[i] = (idx < N) ? g_counts[idx] : 0;
            local += vals[i];
        }
    }
    int x = local;
#pragma unroll
    for (int off = 1; off < 32; off <<= 1) {
        int y = __shfl_up_sync(0xffffffffu, x, off);
        if (lane >= off) x += y;
    }
    if (lane == 31) swarp[wid] = x;
    __syncthreads();
    if (wid == 0 && lane < SCAN_BLK / 32) {
        int v = swarp[lane];
        int xv = v;
#pragma unroll
        for (int off = 1; off < SCAN_BLK / 32; off <<= 1) {
            int y = __shfl_up_sync(0xffu, xv, off);
            if (lane >= off) xv += y;
        }
        swarp[lane] = xv - v;   // exclusive warp prefix
    }
    __syncthreads();
    int within = swarp[wid] + (x - local);       // exclusive prefix within block
    int blktot = 0;
    if (tid == SCAN_BLK - 1) blktot = within + local;

    if (tid == SCAN_BLK - 1) {
        int prev = 0;
        if (b > 0) {
            while (atomicAdd(&g_flags[b - 1], 0) == 0) { }
            prev = g_blocksum[b - 1];
        }
        g_blocksum[b] = prev + blktot;
        __threadfence();
        atomicExch(&g_flags[b], 1);
        s_prev = prev;
        if (b == nblk - 1) g_offsets[N] = prev + blktot;
    }
    __syncthreads();
    int pre = s_prev + within;
    if (start + SCAN_ITEMS <= N) {
#pragma unroll
        for (int i = 0; i < SCAN_ITEMS; i++) {
            g_offsets[start + i] = pre;
            g_cursor[start + i] = pre;
            pre += vals[i];
        }
    } else {
        for (int i = 0; i < SCAN_ITEMS; i++) {
            int idx = start + i;
            if (idx < N) { g_offsets[idx] = pre; g_cursor[idx] = pre; }
            pre += vals[i];
        }
    }
}

// scatter edges into CSR order, 4 edges/thread (R11 config: best measured)
__global__ void scatter_kernel(const int* __restrict__ src,
                               const int* __restrict__ dst,
                               const float* __restrict__ w, int E) {
    int i = (blockIdx.x * blockDim.x + threadIdx.x) * 4;
    if (i + 4 <= E) {
        int4   s  = *(const int4*)(src + i);
        int4   d  = *(const int4*)(dst + i);
        float4 ww = *(const float4*)(w + i);
        int p0 = atomicAdd(&g_cursor[s.x], 1);
        int p1 = atomicAdd(&g_cursor[s.y], 1);
        int p2 = atomicAdd(&g_cursor[s.z], 1);
        int p3 = atomicAdd(&g_cursor[s.w], 1);
        g_edges[p0] = make_int2(d.x, __float_as_int(ww.x));
        g_edges[p1] = make_int2(d.y, __float_as_int(ww.y));
        g_edges[p2] = make_int2(d.z, __float_as_int(ww.z));
        g_edges[p3] = make_int2(d.w, __float_as_int(ww.w));
    } else {
        for (int j = i; j < E; j++) {
            int p = atomicAdd(&g_cursor[src[j]], 1);
            g_edges[p] = make_int2(dst[j], __float_as_int(w[j]));
        }
    }
}

// ---------------------------------------------------------------------------
// Fused aggregate (fp16 gather, depth-2 pipelined) + GEMM (FFMA2) + bias + relu.
// 512 threads (16 warps) share ONE smem W tile -> 32 warps/SM at 2 blocks/SM.
// ONE TILE PER BLOCK: grid = ceil(N/64); HW work-steals later blocks, killing
// the 2-vs-3-tile static-assignment tail of the grid=296 version.
#define ROWS_PER_WARP 4
#define FWARPS 16
#define FTHREADS (FWARPS * 32)          // 512
#define FTILE (FWARPS * ROWS_PER_WARP)  // 64 nodes per block-tile

__global__ __launch_bounds__(FTHREADS, 2)
void fused_agg_gemm_kernel(const float* __restrict__ W,
                           const float* __restrict__ b,
                           float* __restrict__ out, int N) {
    extern __shared__ float sh[];
    float* Ws   = sh;                            // [128][128]
    float* bs   = Ws + D_DIM * D_DIM;            // [128]
    float* aggs = bs + D_DIM;                    // [16][4][128]

    const int tid = threadIdx.x;
    const float4* Wv = (const float4*)W;
    float4* Wsv = (float4*)Ws;
#pragma unroll
    for (int i = 0; i < 8; i++) Wsv[tid + i * FTHREADS] = Wv[tid + i * FTHREADS];
    if (tid < D_DIM) bs[tid] = b[tid];
    __syncthreads();

    const int warp = tid >> 5, lane = tid & 31;
    float* myagg = aggs + warp * ROWS_PER_WARP * D_DIM;
    const uint2* fH = (const uint2*)g_featH;

    const int base = blockIdx.x * FTILE + warp * ROWS_PER_WARP;

    // ---- gather phase: weighted mean per node row, depth-2 pipeline ----
#pragma unroll
    for (int r = 0; r < ROWS_PER_WARP; r++) {
        int node = base + r;
        unsigned long long sAB = 0ull, sCD = 0ull;   // packed (x,y),(z,w)
        float den = 0.f;
        if (node < N) {
            const int beg = g_offsets[node], end = g_offsets[node + 1];
            const int nch = (end - beg + 3) >> 2;    // masked 4-edge chunks
            if (nch > 0) {
#define LDE(a0, a1, a2, a3, jj) do {                                          \
    a0 = ((jj) + 0 < end) ? g_edges[(jj) + 0] : make_int2(0, 0);              \
    a1 = ((jj) + 1 < end) ? g_edges[(jj) + 1] : make_int2(0, 0);              \
    a2 = ((jj) + 2 < end) ? g_edges[(jj) + 2] : make_int2(0, 0);              \
    a3 = ((jj) + 3 < end) ? g_edges[(jj) + 3] : make_int2(0, 0);              \
} while (0)
#define LDH(x0, x1, x2, x3, a0, a1, a2, a3) do {                              \
    x0 = fH[(size_t)(a0).x * 32 + lane];                                      \
    x1 = fH[(size_t)(a1).x * 32 + lane];                                      \
    x2 = fH[(size_t)(a2).x * 32 + lane];                                      \
    x3 = fH[(size_t)(a3).x * 32 + lane];                                      \
} while (0)
#define EDGE_ACC(hh, wsc) do {                                                \
    float2 p_ = __half22float2(*reinterpret_cast<__half2*>(&(hh).x));         \
    float2 q_ = __half22float2(*reinterpret_cast<__half2*>(&(hh).y));         \
    unsigned long long pp_, qq_, ww_;                                         \
    PACK_F32X2(pp_, p_.x, p_.y);                                              \
    PACK_F32X2(qq_, q_.x, q_.y);                                              \
    PACK_F32X2(ww_, (wsc), (wsc));                                            \
    FMA_F32X2(sAB, ww_, pp_, sAB);                                            \
    FMA_F32X2(sCD, ww_, qq_, sCD);                                            \
} while (0)
#define ACC4() do {                                                           \
    float w0_ = __int_as_float(e0.y), w1_ = __int_as_float(e1.y);             \
    float w2_ = __int_as_float(e2.y), w3_ = __int_as_float(e3.y);             \
    EDGE_ACC(h0, w0_); EDGE_ACC(h1, w1_);                                     \
    EDGE_ACC(h2, w2_); EDGE_ACC(h3, w3_);                                     \
    den += (w0_ + w1_) + (w2_ + w3_);                                         \
} while (0)
                int2 e0, e1, e2, e3;      // edges: chunk c (being accumulated)
                int2 f0, f1, f2, f3;      // edges: chunk c+1 (features pending)
                uint2 h0, h1, h2, h3;     // features: chunk c
                int j = beg;
                LDE(e0, e1, e2, e3, j);               // chunk 0 edges
                LDH(h0, h1, h2, h3, e0, e1, e2, e3);  // chunk 0 features
                j += 4;
                if (nch > 1) LDE(f0, f1, f2, f3, j);  // chunk 1 edges
                for (int c = 0; c + 2 < nch; c++) {
                    j += 4;
                    int2 g0, g1, g2, g3;
                    LDE(g0, g1, g2, g3, j);           // chunk c+2 edges
                    uint2 n0, n1, n2, n3;
                    LDH(n0, n1, n2, n3, f0, f1, f2, f3);  // chunk c+1 feats
                    ACC4();                            // accumulate chunk c
                    e0 = f0; e1 = f1; e2 = f2; e3 = f3;
                    f0 = g0; f1 = g1; f2 = g2; f3 = g3;
                    h0 = n0; h1 = n1; h2 = n2; h3 = n3;
                }
                if (nch > 1) {
                    uint2 n0, n1, n2, n3;
                    LDH(n0, n1, n2, n3, f0, f1, f2, f3);  // last chunk feats
                    ACC4();                                // chunk nch-2
                    e0 = f0; e1 = f1; e2 = f2; e3 = f3;
                    h0 = n0; h1 = n1; h2 = n2; h3 = n3;
                }
                ACC4();                                    // last chunk
#undef ACC4
#undef EDGE_ACC
#undef LDH
#undef LDE
            }
        }
        float ax, ay, az, aw;
        UNPACK_F32X2(ax, ay, sAB);
        UNPACK_F32X2(az, aw, sCD);
        float inv = 1.0f / fmaxf(den, 1e-12f);
        *(float4*)(myagg + r * D_DIM + lane * 4) =
            make_float4(ax * inv, ay * inv, az * inv, aw * inv);
    }
    __syncwarp();

    // ---- GEMM phase: packed FFMA2, 4 rows x 4 cols per thread ----
    unsigned long long accA[ROWS_PER_WARP], accB[ROWS_PER_WARP];
#pragma unroll
    for (int r = 0; r < ROWS_PER_WARP; r++) { accA[r] = 0ull; accB[r] = 0ull; }

#pragma unroll 8
    for (int k = 0; k < D_DIM; k += 4) {
        float4 a[ROWS_PER_WARP];
#pragma unroll
        for (int r = 0; r < ROWS_PER_WARP; r++)
            a[r] = *(float4*)(myagg + r * D_DIM + k);
#pragma unroll
        for (int kk = 0; kk < 4; kk++) {
            ulonglong2 wp = *(ulonglong2*)(Ws + (k + kk) * D_DIM + lane * 4);
#pragma unroll
            for (int r = 0; r < ROWS_PER_WARP; r++) {
                float av = ((float*)&a[r])[kk];
                unsigned long long avv;
                PACK_F32X2(avv, av, av);
                FMA_F32X2(accA[r], avv, wp.x, accA[r]);
                FMA_F32X2(accB[r], avv, wp.y, accB[r]);
            }
        }
    }

    float4 bb = *(float4*)(bs + lane * 4);
#pragma unroll
    for (int r = 0; r < ROWS_PER_WARP; r++) {
        int row = base + r;
        if (row < N) {
            float ox, oy, oz, ow;
            UNPACK_F32X2(ox, oy, accA[r]);
            UNPACK_F32X2(oz, ow, accB[r]);
            float4 o;
            o.x = fmaxf(ox + bb.x, 0.f);
            o.y = fmaxf(oy + bb.y, 0.f);
            o.z = fmaxf(oz + bb.z, 0.f);
            o.w = fmaxf(ow + bb.w, 0.f);
            *(float4*)(out + (size_t)row * D_DIM + lane * 4) = o;
        }
    }
}

// ---------------------------------------------------------------------------
extern "C" void kernel_launch(void* const* d_in, const int* in_sizes, int n_in,
                              void* d_out, int out_size) {
    const float* feat = (const float*)d_in[0];   // [N,128]
    const int*   src  = (const int*)d_in[1];     // [E]
    const int*   dst  = (const int*)d_in[2];     // [E]
    const float* w    = (const float*)d_in[3];   // [E]
    const float* W    = (const float*)d_in[4];   // [128,128]
    const float* b    = (const float*)d_in[5];   // [128]
    float* out = (float*)d_out;

    const int N = in_sizes[0] / D_DIM;
    const int E = in_sizes[1];

    {
        int total4 = N * (D_DIM / 4);
        prep_kernel<<<(total4 + 255) / 256, 256>>>(feat, total4, N);
    }
    hist_kernel<<<((E + 3) / 4 + 255) / 256, 256>>>(src, E);

    const int nblk = (N + SCAN_TILE - 1) / SCAN_TILE;   // 13 (<= #SMs: safe lookback)
    scan_kernel<<<nblk, SCAN_BLK>>>(N, nblk);

    scatter_kernel<<<((E + 3) / 4 + 255) / 256, 256>>>(src, dst, w, E);

    const int tiles = (N + FTILE - 1) / FTILE;          // 782: one tile per block
    const int smem = (D_DIM * D_DIM + D_DIM +
                      FWARPS * ROWS_PER_WARP * D_DIM) * (int)sizeof(float);  // 98816 B
    cudaFuncSetAttribute(fused_agg_gemm_kernel,
                         cudaFuncAttributeMaxDynamicSharedMemorySize, smem);
    fused_agg_gemm_kernel<<<tiles, FTHREADS, smem>>>(W, b, out, N);
}

// round 16
// speedup vs baseline: 1.5761x; 1.1031x over previous
#include <cuda_runtime.h>
#include <cuda_fp16.h>

// Fixed problem shape: N=50000, E=1600000, D=U=128.
#define MAX_N 50048
#define MAX_E 1600000
#define D_DIM 128

#define SCAN_BLK   256
#define SCAN_ITEMS 16
#define SCAN_TILE  (SCAN_BLK * SCAN_ITEMS)   // 4096
#define MAX_SCAN_BLKS 16

// Packed fp32x2 ops (Blackwell): one issue slot, two IEEE fp32 ops.
#define FMA_F32X2(d, a, b, c) \
    asm("fma.rn.f32x2 %0, %1, %2, %3;" : "=l"(d) : "l"(a), "l"(b), "l"(c))
#define ADD_F32X2(d, a, b) \
    asm("add.rn.f32x2 %0, %1, %2;" : "=l"(d) : "l"(a), "l"(b))
#define MUL_F32X2(d, a, b) \
    asm("mul.rn.f32x2 %0, %1, %2;" : "=l"(d) : "l"(a), "l"(b))
#define PACK_F32X2(d, lo, hi) \
    asm("mov.b64 %0, {%1, %2};" : "=l"(d) : "f"(lo), "f"(hi))
#define UNPACK_F32X2(lo, hi, s) \
    asm("mov.b64 {%0, %1}, %2;" : "=f"(lo), "=f"(hi) : "l"(s))

// Scratch (__device__ globals; no allocations allowed).
__device__ int    g_counts[MAX_N];
__device__ int    g_offsets[MAX_N + 1];
__device__ int    g_cursor[MAX_N];
__device__ int    g_blocksum[MAX_SCAN_BLKS];   // inclusive per-block sums
__device__ int    g_flags[MAX_SCAN_BLKS];      // lookback ready flags
__device__ int2   g_edges[MAX_E];              // (dst, weight bits), CSR by src
__device__ __half g_featH[(size_t)MAX_N * D_DIM];

// ---------------------------------------------------------------------------
// fp32 -> fp16 feature table, fused with zeroing counts + scan flags.
__global__ void prep_kernel(const float* __restrict__ feat, int total4, int N) {
    int i = blockIdx.x * blockDim.x + threadIdx.x;
    if (i < total4) {
        float4 v = ((const float4*)feat)[i];
        __half2 h0 = __floats2half2_rn(v.x, v.y);
        __half2 h1 = __floats2half2_rn(v.z, v.w);
        uint2 u;
        *reinterpret_cast<__half2*>(&u.x) = h0;
        *reinterpret_cast<__half2*>(&u.y) = h1;
        ((uint2*)g_featH)[i] = u;
    }
    if (i < N) g_counts[i] = 0;
    if (i < MAX_SCAN_BLKS) { g_flags[i] = 0; g_blocksum[i] = 0; }
}

// histogram of edge_src, 4 edges/thread
__global__ void hist_kernel(const int* __restrict__ src, int E) {
    int i = (blockIdx.x * blockDim.x + threadIdx.x) * 4;
    if (i + 4 <= E) {
        int4 s = *(const int4*)(src + i);
        atomicAdd(&g_counts[s.x], 1);
        atomicAdd(&g_counts[s.y], 1);
        atomicAdd(&g_counts[s.z], 1);
        atomicAdd(&g_counts[s.w], 1);
    } else {
        for (int j = i; j < E; j++) atomicAdd(&g_counts[src[j]], 1);
    }
}

// ---- single-pass exclusive scan (decoupled lookback; nblk=13 <= #SMs) ----
__global__ void scan_kernel(int N, int nblk) {
    __shared__ int swarp[SCAN_BLK / 32];
    __shared__ int s_prev;
    const int tid = threadIdx.x, lane = tid & 31, wid = tid >> 5;
    const int b = blockIdx.x;
    int start = b * SCAN_TILE + tid * SCAN_ITEMS;

    int vals[SCAN_ITEMS];
    int local = 0;
    if (start + SCAN_ITEMS <= N) {
#pragma unroll
        for (int v = 0; v < SCAN_ITEMS / 4; v++) {
            int4 c = *(const int4*)(g_counts + start + v * 4);
            vals[v * 4 + 0] = c.x; vals[v * 4 + 1] = c.y;
            vals[v * 4 + 2] = c.z; vals[v * 4 + 3] = c.w;
            local += c.x + c.y + c.z + c.w;
        }
    } else {
#pragma unroll
        for (int i = 0; i < SCAN_ITEMS; i++) {
            int idx = start + i;
            vals[i] = (idx < N) ? g_counts[idx] : 0;
            local += vals[i];
        }
    }
    int x = local;
#pragma unroll
    for (int off = 1; off < 32; off <<= 1) {
        int y = __shfl_up_sync(0xffffffffu, x, off);
        if (lane >= off) x += y;
    }
    if (lane == 31) swarp[wid] = x;
    __syncthreads();
    if (wid == 0 && lane < SCAN_BLK / 32) {
        int v = swarp[lane];
        int xv = v;
#pragma unroll
        for (int off = 1; off < SCAN_BLK / 32; off <<= 1) {
            int y = __shfl_up_sync(0xffu, xv, off);
            if (lane >= off) xv += y;
        }
        swarp[lane] = xv - v;   // exclusive warp prefix
    }
    __syncthreads();
    int within = swarp[wid] + (x - local);       // exclusive prefix within block
    int blktot = 0;
    if (tid == SCAN_BLK - 1) blktot = within + local;

    if (tid == SCAN_BLK - 1) {
        int prev = 0;
        if (b > 0) {
            while (atomicAdd(&g_flags[b - 1], 0) == 0) { }
            prev = g_blocksum[b - 1];
        }
        g_blocksum[b] = prev + blktot;
        __threadfence();
        atomicExch(&g_flags[b], 1);
        s_prev = prev;
        if (b == nblk - 1) g_offsets[N] = prev + blktot;
    }
    __syncthreads();
    int pre = s_prev + within;
    if (start + SCAN_ITEMS <= N) {
#pragma unroll
        for (int i = 0; i < SCAN_ITEMS; i++) {
            g_offsets[start + i] = pre;
            g_cursor[start + i] = pre;
            pre += vals[i];
        }
    } else {
        for (int i = 0; i < SCAN_ITEMS; i++) {
            int idx = start + i;
            if (idx < N) { g_offsets[idx] = pre; g_cursor[idx] = pre; }
            pre += vals[i];
        }
    }
}

// scatter edges into CSR order, 4 edges/thread (best measured config)
__global__ void scatter_kernel(const int* __restrict__ src,
                               const int* __restrict__ dst,
                               const float* __restrict__ w, int E) {
    int i = (blockIdx.x * blockDim.x + threadIdx.x) * 4;
    if (i + 4 <= E) {
        int4   s  = *(const int4*)(src + i);
        int4   d  = *(const int4*)(dst + i);
        float4 ww = *(const float4*)(w + i);
        int p0 = atomicAdd(&g_cursor[s.x], 1);
        int p1 = atomicAdd(&g_cursor[s.y], 1);
        int p2 = atomicAdd(&g_cursor[s.z], 1);
        int p3 = atomicAdd(&g_cursor[s.w], 1);
        g_edges[p0] = make_int2(d.x, __float_as_int(ww.x));
        g_edges[p1] = make_int2(d.y, __float_as_int(ww.y));
        g_edges[p2] = make_int2(d.z, __float_as_int(ww.z));
        g_edges[p3] = make_int2(d.w, __float_as_int(ww.w));
    } else {
        for (int j = i; j < E; j++) {
            int p = atomicAdd(&g_cursor[src[j]], 1);
            g_edges[p] = make_int2(dst[j], __float_as_int(w[j]));
        }
    }
}

// ---------------------------------------------------------------------------
// Fused aggregate + GEMM. Gather uses HALF-WARP edge mapping:
//   lanes 0-15 process edges {j, j+1}, lanes 16-31 process {j+2, j+3};
//   each lane reads uint4 (8 fp16 dims) of its edge's row via LDG.128.
// Halves are combined with shfl_xor(16) + add.f32x2 at row end.
// Persistent grid (296 = 2/SM), 512 threads, one shared W tile.
#define ROWS_PER_WARP 4
#define FWARPS 16
#define FTHREADS (FWARPS * 32)          // 512
#define FTILE (FWARPS * ROWS_PER_WARP)  // 64 nodes per block-tile

__global__ __launch_bounds__(FTHREADS, 2)
void fused_agg_gemm_kernel(const float* __restrict__ W,
                           const float* __restrict__ b,
                           float* __restrict__ out, int N) {
    extern __shared__ float sh[];
    float* Ws   = sh;                            // [128][128]
    float* bs   = Ws + D_DIM * D_DIM;            // [128]
    float* aggs = bs + D_DIM;                    // [16][4][128]

    const int tid = threadIdx.x;
    const float4* Wv = (const float4*)W;
    float4* Wsv = (float4*)Ws;
#pragma unroll
    for (int i = 0; i < 8; i++) Wsv[tid + i * FTHREADS] = Wv[tid + i * FTHREADS];
    if (tid < D_DIM) bs[tid] = b[tid];
    __syncthreads();

    const int warp = tid >> 5, lane = tid & 31;
    const int half = lane >> 4;          // which edge pair this lane handles
    const int sub  = lane & 15;          // 16B sub-chunk of the feature row
    float* myagg = aggs + warp * ROWS_PER_WARP * D_DIM;
    const uint4* fH4 = (const uint4*)g_featH;    // 16 uint4 per row

    const int tiles = (N + FTILE - 1) / FTILE;
    for (int t = blockIdx.x; t < tiles; t += gridDim.x) {
        const int base = t * FTILE + warp * ROWS_PER_WARP;

        // ---- gather phase ----
#pragma unroll
        for (int r = 0; r < ROWS_PER_WARP; r++) {
            int node = base + r;
            unsigned long long s0 = 0ull, s1 = 0ull, s2 = 0ull, s3 = 0ull;
            float den = 0.f;
            if (node < N) {
                const int beg = g_offsets[node], end = g_offsets[node + 1];
                const int nch = (end - beg + 3) >> 2;    // 4-edge chunks (2/half)
                if (nch > 0) {
// lane's two edges of the chunk starting at jj (masked OOB -> (0,0))
#define LDE2(a0, a1, jj) do {                                                 \
    int ia_ = (jj) + (half << 1);                                             \
    a0 = (ia_ < end)     ? g_edges[ia_]     : make_int2(0, 0);                \
    a1 = (ia_ + 1 < end) ? g_edges[ia_ + 1] : make_int2(0, 0);                \
} while (0)
#define LDF2(x0, x1, a0, a1) do {                                             \
    x0 = fH4[(a0).x * 16 + sub];                                              \
    x1 = fH4[(a1).x * 16 + sub];                                              \
} while (0)
#define ACCE(ff, wsc) do {                                                    \
    unsigned long long ww_;                                                   \
    PACK_F32X2(ww_, (wsc), (wsc));                                            \
    const __half2* hp_ = reinterpret_cast<const __half2*>(&(ff));             \
    float2 p0_ = __half22float2(hp_[0]);                                      \
    float2 p1_ = __half22float2(hp_[1]);                                      \
    float2 p2_ = __half22float2(hp_[2]);                                      \
    float2 p3_ = __half22float2(hp_[3]);                                      \
    unsigned long long t_;                                                    \
    PACK_F32X2(t_, p0_.x, p0_.y); FMA_F32X2(s0, ww_, t_, s0);                 \
    PACK_F32X2(t_, p1_.x, p1_.y); FMA_F32X2(s1, ww_, t_, s1);                 \
    PACK_F32X2(t_, p2_.x, p2_.y); FMA_F32X2(s2, ww_, t_, s2);                 \
    PACK_F32X2(t_, p3_.x, p3_.y); FMA_F32X2(s3, ww_, t_, s3);                 \
} while (0)
#define ACC2() do {                                                           \
    float w0_ = __int_as_float(e0.y), w1_ = __int_as_float(e1.y);             \
    ACCE(f0, w0_); ACCE(f1, w1_);                                             \
    den += w0_ + w1_;                                                         \
} while (0)
                    int2 e0, e1;          // lane's edges: chunk c
                    int2 g0, g1;          // lane's edges: chunk c+1
                    uint4 f0, f1;         // features: chunk c
                    int j = beg;
                    LDE2(e0, e1, j);
                    LDF2(f0, f1, e0, e1);
                    j += 4;
                    if (nch > 1) LDE2(g0, g1, j);
                    for (int c = 0; c + 2 < nch; c++) {
                        j += 4;
                        int2 k0, k1;
                        LDE2(k0, k1, j);                 // chunk c+2 edges
                        uint4 n0, n1;
                        LDF2(n0, n1, g0, g1);            // chunk c+1 feats
                        ACC2();                           // accumulate chunk c
                        e0 = g0; e1 = g1; g0 = k0; g1 = k1;
                        f0 = n0; f1 = n1;
                    }
                    if (nch > 1) {
                        uint4 n0, n1;
                        LDF2(n0, n1, g0, g1);
                        ACC2();
                        e0 = g0; e1 = g1; f0 = n0; f1 = n1;
                    }
                    ACC2();
#undef ACC2
#undef ACCE
#undef LDF2
#undef LDE2
                }
            }
            // combine the two half-warp partial sums (packed adds)
            {
                unsigned long long o;
                o = __shfl_xor_sync(0xffffffffu, s0, 16); ADD_F32X2(s0, s0, o);
                o = __shfl_xor_sync(0xffffffffu, s1, 16); ADD_F32X2(s1, s1, o);
                o = __shfl_xor_sync(0xffffffffu, s2, 16); ADD_F32X2(s2, s2, o);
                o = __shfl_xor_sync(0xffffffffu, s3, 16); ADD_F32X2(s3, s3, o);
                den += __shfl_xor_sync(0xffffffffu, den, 16);
            }
            float inv = 1.0f / fmaxf(den, 1e-12f);
            unsigned long long invp;
            PACK_F32X2(invp, inv, inv);
            unsigned long long va = half ? s2 : s0;
            unsigned long long vb = half ? s3 : s1;
            MUL_F32X2(va, va, invp);
            MUL_F32X2(vb, vb, invp);
            float4 o4;
            UNPACK_F32X2(o4.x, o4.y, va);
            UNPACK_F32X2(o4.z, o4.w, vb);
            *(float4*)(myagg + r * D_DIM + sub * 8 + half * 4) = o4;
        }
        __syncwarp();

        // ---- GEMM phase: packed FFMA2, 4 rows x 4 cols per thread ----
        unsigned long long accA[ROWS_PER_WARP], accB[ROWS_PER_WARP];
#pragma unroll
        for (int r = 0; r < ROWS_PER_WARP; r++) { accA[r] = 0ull; accB[r] = 0ull; }

#pragma unroll 8
        for (int k = 0; k < D_DIM; k += 4) {
            float4 a[ROWS_PER_WARP];
#pragma unroll
            for (int r = 0; r < ROWS_PER_WARP; r++)
                a[r] = *(float4*)(myagg + r * D_DIM + k);
#pragma unroll
            for (int kk = 0; kk < 4; kk++) {
                ulonglong2 wp = *(ulonglong2*)(Ws + (k + kk) * D_DIM + lane * 4);
#pragma unroll
                for (int r = 0; r < ROWS_PER_WARP; r++) {
                    float av = ((float*)&a[r])[kk];
                    unsigned long long avv;
                    PACK_F32X2(avv, av, av);
                    FMA_F32X2(accA[r], avv, wp.x, accA[r]);
                    FMA_F32X2(accB[r], avv, wp.y, accB[r]);
                }
            }
        }

        float4 bb = *(float4*)(bs + lane * 4);
#pragma unroll
        for (int r = 0; r < ROWS_PER_WARP; r++) {
            int row = base + r;
            if (row < N) {
                float ox, oy, oz, ow;
                UNPACK_F32X2(ox, oy, accA[r]);
                UNPACK_F32X2(oz, ow, accB[r]);
                float4 o;
                o.x = fmaxf(ox + bb.x, 0.f);
                o.y = fmaxf(oy + bb.y, 0.f);
                o.z = fmaxf(oz + bb.z, 0.f);
                o.w = fmaxf(ow + bb.w, 0.f);
                *(float4*)(out + (size_t)row * D_DIM + lane * 4) = o;
            }
        }
        __syncwarp();
    }
}

// ---------------------------------------------------------------------------
extern "C" void kernel_launch(void* const* d_in, const int* in_sizes, int n_in,
                              void* d_out, int out_size) {
    const float* feat = (const float*)d_in[0];   // [N,128]
    const int*   src  = (const int*)d_in[1];     // [E]
    const int*   dst  = (const int*)d_in[2];     // [E]
    const float* w    = (const float*)d_in[3];   // [E]
    const float* W    = (const float*)d_in[4];   // [128,128]
    const float* b    = (const float*)d_in[5];   // [128]
    float* out = (float*)d_out;

    const int N = in_sizes[0] / D_DIM;
    const int E = in_sizes[1];

    {
        int total4 = N * (D_DIM / 4);
        prep_kernel<<<(total4 + 255) / 256, 256>>>(feat, total4, N);
    }
    hist_kernel<<<((E + 3) / 4 + 255) / 256, 256>>>(src, E);

    const int nblk = (N + SCAN_TILE - 1) / SCAN_TILE;   // 13 (<= #SMs: safe lookback)
    scan_kernel<<<nblk, SCAN_BLK>>>(N, nblk);

    scatter_kernel<<<((E + 3) / 4 + 255) / 256, 256>>>(src, dst, w, E);

    const int smem = (D_DIM * D_DIM + D_DIM +
                      FWARPS * ROWS_PER_WARP * D_DIM) * (int)sizeof(float);  // 98816 B
    cudaFuncSetAttribute(fused_agg_gemm_kernel,
                         cudaFuncAttributeMaxDynamicSharedMemorySize, smem);
    fused_agg_gemm_kernel<<<296, FTHREADS, smem>>>(W, b, out, N);
}

// round 17
// speedup vs baseline: 1.6720x; 1.0608x over previous
#include <cuda_runtime.h>
#include <cuda_fp16.h>

// Fixed problem shape: N=50000, E=1600000, D=U=128.
#define MAX_N 50048
#define MAX_E 1600000
#define D_DIM 128

#define SCAN_BLK   256
#define SCAN_ITEMS 16
#define SCAN_TILE  (SCAN_BLK * SCAN_ITEMS)   // 4096
#define MAX_SCAN_BLKS 16

// Packed fp32x2 ops (Blackwell): one issue slot, two IEEE fp32 ops.
#define FMA_F32X2(d, a, b, c) \
    asm("fma.rn.f32x2 %0, %1, %2, %3;" : "=l"(d) : "l"(a), "l"(b), "l"(c))
#define ADD_F32X2(d, a, b) \
    asm("add.rn.f32x2 %0, %1, %2;" : "=l"(d) : "l"(a), "l"(b))
#define MUL_F32X2(d, a, b) \
    asm("mul.rn.f32x2 %0, %1, %2;" : "=l"(d) : "l"(a), "l"(b))
#define PACK_F32X2(d, lo, hi) \
    asm("mov.b64 %0, {%1, %2};" : "=l"(d) : "f"(lo), "f"(hi))
#define UNPACK_F32X2(lo, hi, s) \
    asm("mov.b64 {%0, %1}, %2;" : "=f"(lo), "=f"(hi) : "l"(s))

// Scratch (__device__ globals; zero-initialized at module load; the fused
// kernel re-zeroes counts/flags at the end of every run so each graph replay
// starts from the same state).
__device__ int    g_counts[MAX_N];
__device__ int    g_offsets[MAX_N + 1];
__device__ int    g_cursor[MAX_N];
__device__ int    g_blocksum[MAX_SCAN_BLKS];   // inclusive per-block sums
__device__ int    g_flags[MAX_SCAN_BLKS];      // lookback ready flags
__device__ int2   g_edges[MAX_E];              // (dst, weight bits), CSR by src
__device__ __half g_featH[(size_t)MAX_N * D_DIM];

// ---------------------------------------------------------------------------
// Fused prep + histogram (independent input streams, one launch):
//   - fp32 -> fp16 feature table (one float4 per thread)
//   - histogram of edge_src (4 edges per thread, first E/4 threads)
// Requires g_counts == 0 on entry (established by fused kernel's cleanup).
__global__ void prep_hist_kernel(const float* __restrict__ feat, int total4,
                                 const int* __restrict__ src, int E) {
    int i = blockIdx.x * blockDim.x + threadIdx.x;
    if (i < total4) {
        float4 v = ((const float4*)feat)[i];
        __half2 h0 = __floats2half2_rn(v.x, v.y);
        __half2 h1 = __floats2half2_rn(v.z, v.w);
        uint2 u;
        *reinterpret_cast<__half2*>(&u.x) = h0;
        *reinterpret_cast<__half2*>(&u.y) = h1;
        ((uint2*)g_featH)[i] = u;
    }
    int e = i * 4;
    if (e + 4 <= E) {
        int4 s = *(const int4*)(src + e);
        atomicAdd(&g_counts[s.x], 1);
        atomicAdd(&g_counts[s.y], 1);
        atomicAdd(&g_counts[s.z], 1);
        atomicAdd(&g_counts[s.w], 1);
    } else if (e < E) {
        for (int j = e; j < E; j++) atomicAdd(&g_counts[src[j]], 1);
    }
}

// ---- single-pass exclusive scan (decoupled lookback; nblk=13 <= #SMs) ----
__global__ void scan_kernel(int N, int nblk) {
    __shared__ int swarp[SCAN_BLK / 32];
    __shared__ int s_prev;
    const int tid = threadIdx.x, lane = tid & 31, wid = tid >> 5;
    const int b = blockIdx.x;
    int start = b * SCAN_TILE + tid * SCAN_ITEMS;

    int vals[SCAN_ITEMS];
    int local = 0;
    if (start + SCAN_ITEMS <= N) {
#pragma unroll
        for (int v = 0; v < SCAN_ITEMS / 4; v++) {
            int4 c = *(const int4*)(g_counts + start + v * 4);
            vals[v * 4 + 0] = c.x; vals[v * 4 + 1] = c.y;
            vals[v * 4 + 2] = c.z; vals[v * 4 + 3] = c.w;
            local += c.x + c.y + c.z + c.w;
        }
    } else {
#pragma unroll
        for (int i = 0; i < SCAN_ITEMS; i++) {
            int idx = start + i;
            vals[i] = (idx < N) ? g_counts[idx] : 0;
            local += vals[i];
        }
    }
    int x = local;
#pragma unroll
    for (int off = 1; off < 32; off <<= 1) {
        int y = __shfl_up_sync(0xffffffffu, x, off);
        if (lane >= off) x += y;
    }
    if (lane == 31) swarp[wid] = x;
    __syncthreads();
    if (wid == 0 && lane < SCAN_BLK / 32) {
        int v = swarp[lane];
        int xv = v;
#pragma unroll
        for (int off = 1; off < SCAN_BLK / 32; off <<= 1) {
            int y = __shfl_up_sync(0xffu, xv, off);
            if (lane >= off) xv += y;
        }
        swarp[lane] = xv - v;   // exclusive warp prefix
    }
    __syncthreads();
    int within = swarp[wid] + (x - local);       // exclusive prefix within block
    int blktot = 0;
    if (tid == SCAN_BLK - 1) blktot = within + local;

    if (tid == SCAN_BLK - 1) {
        int prev = 0;
        if (b > 0) {
            while (atomicAdd(&g_flags[b - 1], 0) == 0) { }
            prev = g_blocksum[b - 1];
        }
        g_blocksum[b] = prev + blktot;
        __threadfence();
        atomicExch(&g_flags[b], 1);
        s_prev = prev;
        if (b == nblk - 1) g_offsets[N] = prev + blktot;
    }
    __syncthreads();
    int pre = s_prev + within;
    if (start + SCAN_ITEMS <= N) {
#pragma unroll
        for (int i = 0; i < SCAN_ITEMS; i++) {
            g_offsets[start + i] = pre;
            g_cursor[start + i] = pre;
            pre += vals[i];
        }
    } else {
        for (int i = 0; i < SCAN_ITEMS; i++) {
            int idx = start + i;
            if (idx < N) { g_offsets[idx] = pre; g_cursor[idx] = pre; }
            pre += vals[i];
        }
    }
}

// scatter edges into CSR order, 4 edges/thread (best measured config)
__global__ void scatter_kernel(const int* __restrict__ src,
                               const int* __restrict__ dst,
                               const float* __restrict__ w, int E) {
    int i = (blockIdx.x * blockDim.x + threadIdx.x) * 4;
    if (i + 4 <= E) {
        int4   s  = *(const int4*)(src + i);
        int4   d  = *(const int4*)(dst + i);
        float4 ww = *(const float4*)(w + i);
        int p0 = atomicAdd(&g_cursor[s.x], 1);
        int p1 = atomicAdd(&g_cursor[s.y], 1);
        int p2 = atomicAdd(&g_cursor[s.z], 1);
        int p3 = atomicAdd(&g_cursor[s.w], 1);
        g_edges[p0] = make_int2(d.x, __float_as_int(ww.x));
        g_edges[p1] = make_int2(d.y, __float_as_int(ww.y));
        g_edges[p2] = make_int2(d.z, __float_as_int(ww.z));
        g_edges[p3] = make_int2(d.w, __float_as_int(ww.w));
    } else {
        for (int j = i; j < E; j++) {
            int p = atomicAdd(&g_cursor[src[j]], 1);
            g_edges[p] = make_int2(dst[j], __float_as_int(w[j]));
        }
    }
}

// ---------------------------------------------------------------------------
// Fused aggregate + GEMM. Gather uses HALF-WARP edge mapping:
//   lanes 0-15 process edges {j, j+1}, lanes 16-31 process {j+2, j+3};
//   each lane reads uint4 (8 fp16 dims) of its edge's row via LDG.128.
// Halves are combined with shfl_xor(16) + add.f32x2 at row end.
// Persistent grid (296 = 2/SM), 512 threads, one shared W tile.
// At the end, re-zeroes g_counts/g_flags/g_blocksum for the next run.
#define ROWS_PER_WARP 4
#define FWARPS 16
#define FTHREADS (FWARPS * 32)          // 512
#define FTILE (FWARPS * ROWS_PER_WARP)  // 64 nodes per block-tile

__global__ __launch_bounds__(FTHREADS, 2)
void fused_agg_gemm_kernel(const float* __restrict__ W,
                           const float* __restrict__ b,
                           float* __restrict__ out, int N) {
    extern __shared__ float sh[];
    float* Ws   = sh;                            // [128][128]
    float* bs   = Ws + D_DIM * D_DIM;            // [128]
    float* aggs = bs + D_DIM;                    // [16][4][128]

    const int tid = threadIdx.x;
    const float4* Wv = (const float4*)W;
    float4* Wsv = (float4*)Ws;
#pragma unroll
    for (int i = 0; i < 8; i++) Wsv[tid + i * FTHREADS] = Wv[tid + i * FTHREADS];
    if (tid < D_DIM) bs[tid] = b[tid];
    __syncthreads();

    const int warp = tid >> 5, lane = tid & 31;
    const int half = lane >> 4;          // which edge pair this lane handles
    const int sub  = lane & 15;          // 16B sub-chunk of the feature row
    float* myagg = aggs + warp * ROWS_PER_WARP * D_DIM;
    const uint4* fH4 = (const uint4*)g_featH;    // 16 uint4 per row

    const int tiles = (N + FTILE - 1) / FTILE;
    for (int t = blockIdx.x; t < tiles; t += gridDim.x) {
        const int base = t * FTILE + warp * ROWS_PER_WARP;

        // ---- gather phase ----
#pragma unroll
        for (int r = 0; r < ROWS_PER_WARP; r++) {
            int node = base + r;
            unsigned long long s0 = 0ull, s1 = 0ull, s2 = 0ull, s3 = 0ull;
            float den = 0.f;
            if (node < N) {
                const int beg = g_offsets[node], end = g_offsets[node + 1];
                const int nch = (end - beg + 3) >> 2;    // 4-edge chunks (2/half)
                if (nch > 0) {
// lane's two edges of the chunk starting at jj (masked OOB -> (0,0))
#define LDE2(a0, a1, jj) do {                                                 \
    int ia_ = (jj) + (half << 1);                                             \
    a0 = (ia_ < end)     ? g_edges[ia_]     : make_int2(0, 0);                \
    a1 = (ia_ + 1 < end) ? g_edges[ia_ + 1] : make_int2(0, 0);                \
} while (0)
#define LDF2(x0, x1, a0, a1) do {                                             \
    x0 = fH4[(a0).x * 16 + sub];                                              \
    x1 = fH4[(a1).x * 16 + sub];                                              \
} while (0)
#define ACCE(ff, wsc) do {                                                    \
    unsigned long long ww_;                                                   \
    PACK_F32X2(ww_, (wsc), (wsc));                                            \
    const __half2* hp_ = reinterpret_cast<const __half2*>(&(ff));             \
    float2 p0_ = __half22float2(hp_[0]);                                      \
    float2 p1_ = __half22float2(hp_[1]);                                      \
    float2 p2_ = __half22float2(hp_[2]);                                      \
    float2 p3_ = __half22float2(hp_[3]);                                      \
    unsigned long long t_;                                                    \
    PACK_F32X2(t_, p0_.x, p0_.y); FMA_F32X2(s0, ww_, t_, s0);                 \
    PACK_F32X2(t_, p1_.x, p1_.y); FMA_F32X2(s1, ww_, t_, s1);                 \
    PACK_F32X2(t_, p2_.x, p2_.y); FMA_F32X2(s2, ww_, t_, s2);                 \
    PACK_F32X2(t_, p3_.x, p3_.y); FMA_F32X2(s3, ww_, t_, s3);                 \
} while (0)
#define ACC2() do {                                                           \
    float w0_ = __int_as_float(e0.y), w1_ = __int_as_float(e1.y);             \
    ACCE(f0, w0_); ACCE(f1, w1_);                                             \
    den += w0_ + w1_;                                                         \
} while (0)
                    int2 e0, e1;          // lane's edges: chunk c
                    int2 g0, g1;          // lane's edges: chunk c+1
                    uint4 f0, f1;         // features: chunk c
                    int j = beg;
                    LDE2(e0, e1, j);
                    LDF2(f0, f1, e0, e1);
                    j += 4;
                    if (nch > 1) LDE2(g0, g1, j);
                    for (int c = 0; c + 2 < nch; c++) {
                        j += 4;
                        int2 k0, k1;
                        LDE2(k0, k1, j);                 // chunk c+2 edges
                        uint4 n0, n1;
                        LDF2(n0, n1, g0, g1);            // chunk c+1 feats
                        ACC2();                           // accumulate chunk c
                        e0 = g0; e1 = g1; g0 = k0; g1 = k1;
                        f0 = n0; f1 = n1;
                    }
                    if (nch > 1) {
                        uint4 n0, n1;
                        LDF2(n0, n1, g0, g1);
                        ACC2();
                        e0 = g0; e1 = g1; f0 = n0; f1 = n1;
                    }
                    ACC2();
#undef ACC2
#undef ACCE
#undef LDF2
#undef LDE2
                }
            }
            // combine the two half-warp partial sums (packed adds)
            {
                unsigned long long o;
                o = __shfl_xor_sync(0xffffffffu, s0, 16); ADD_F32X2(s0, s0, o);
                o = __shfl_xor_sync(0xffffffffu, s1, 16); ADD_F32X2(s1, s1, o);
                o = __shfl_xor_sync(0xffffffffu, s2, 16); ADD_F32X2(s2, s2, o);
                o = __shfl_xor_sync(0xffffffffu, s3, 16); ADD_F32X2(s3, s3, o);
                den += __shfl_xor_sync(0xffffffffu, den, 16);
            }
            float inv = 1.0f / fmaxf(den, 1e-12f);
            unsigned long long invp;
            PACK_F32X2(invp, inv, inv);
            unsigned long long va = half ? s2 : s0;
            unsigned long long vb = half ? s3 : s1;
            MUL_F32X2(va, va, invp);
            MUL_F32X2(vb, vb, invp);
            float4 o4;
            UNPACK_F32X2(o4.x, o4.y, va);
            UNPACK_F32X2(o4.z, o4.w, vb);
            *(float4*)(myagg + r * D_DIM + sub * 8 + half * 4) = o4;
        }
        __syncwarp();

        // ---- GEMM phase: packed FFMA2, 4 rows x 4 cols per thread ----
        unsigned long long accA[ROWS_PER_WARP], accB[ROWS_PER_WARP];
#pragma unroll
        for (int r = 0; r < ROWS_PER_WARP; r++) { accA[r] = 0ull; accB[r] = 0ull; }

#pragma unroll 8
        for (int k = 0; k < D_DIM; k += 4) {
            float4 a[ROWS_PER_WARP];
#pragma unroll
            for (int r = 0; r < ROWS_PER_WARP; r++)
                a[r] = *(float4*)(myagg + r * D_DIM + k);
#pragma unroll
            for (int kk = 0; kk < 4; kk++) {
                ulonglong2 wp = *(ulonglong2*)(Ws + (k + kk) * D_DIM + lane * 4);
#pragma unroll
                for (int r = 0; r < ROWS_PER_WARP; r++) {
                    float av = ((float*)&a[r])[kk];
                    unsigned long long avv;
                    PACK_F32X2(avv, av, av);
                    FMA_F32X2(accA[r], avv, wp.x, accA[r]);
                    FMA_F32X2(accB[r], avv, wp.y, accB[r]);
                }
            }
        }

        float4 bb = *(float4*)(bs + lane * 4);
#pragma unroll
        for (int r = 0; r < ROWS_PER_WARP; r++) {
            int row = base + r;
            if (row < N) {
                float ox, oy, oz, ow;
                UNPACK_F32X2(ox, oy, accA[r]);
                UNPACK_F32X2(oz, ow, accB[r]);
                float4 o;
                o.x = fmaxf(ox + bb.x, 0.f);
                o.y = fmaxf(oy + bb.y, 0.f);
                o.z = fmaxf(oz + bb.z, 0.f);
                o.w = fmaxf(ow + bb.w, 0.f);
                *(float4*)(out + (size_t)row * D_DIM + lane * 4) = o;
            }
        }
        __syncwarp();
    }

    // ---- cleanup: restore the "counts/flags zeroed" invariant for the next
    // run (nothing reads g_counts after scan; safe to zero here).
    {
        int gtid = blockIdx.x * FTHREADS + tid;
        int stride = gridDim.x * FTHREADS;
        for (int i = gtid; i < N; i += stride) g_counts[i] = 0;
        if (gtid < MAX_SCAN_BLKS) { g_flags[gtid] = 0; g_blocksum[gtid] = 0; }
    }
}

// ---------------------------------------------------------------------------
extern "C" void kernel_launch(void* const* d_in, const int* in_sizes, int n_in,
                              void* d_out, int out_size) {
    const float* feat = (const float*)d_in[0];   // [N,128]
    const int*   src  = (const int*)d_in[1];     // [E]
    const int*   dst  = (const int*)d_in[2];     // [E]
    const float* w    = (const float*)d_in[3];   // [E]
    const float* W    = (const float*)d_in[4];   // [128,128]
    const float* b    = (const float*)d_in[5];   // [128]
    float* out = (float*)d_out;

    const int N = in_sizes[0] / D_DIM;
    const int E = in_sizes[1];

    {
        int total4 = N * (D_DIM / 4);            // 1.6M convert items
        int nhist  = (E + 3) / 4;                // 400K hist threads
        int nthr   = total4 > nhist ? total4 : nhist;
        prep_hist_kernel<<<(nthr + 255) / 256, 256>>>(feat, total4, src, E);
    }

    const int nblk = (N + SCAN_TILE - 1) / SCAN_TILE;   // 13 (<= #SMs: safe lookback)
    scan_kernel<<<nblk, SCAN_BLK>>>(N, nblk);

    scatter_kernel<<<((E + 3) / 4 + 255) / 256, 256>>>(src, dst, w, E);

    const int smem = (D_DIM * D_DIM + D_DIM +
                      FWARPS * ROWS_PER_WARP * D_DIM) * (int)sizeof(float);  // 98816 B
    cudaFuncSetAttribute(fused_agg_gemm_kernel,
                         cudaFuncAttributeMaxDynamicSharedMemorySize, smem);
    fused_agg_gemm_kernel<<<296, FTHREADS, smem>>>(W, b, out, N);
}